// round 12
// baseline (speedup 1.0000x reference)
#include <cuda_runtime.h>

// Problem constants
#define NPTS 16384
#define KNN  16
#define HDIM 64
#define CDIM 10

// Spatial grid: h=0.3 over [-4.8, 4.8]^3
#define GRID  32
#define NCELL (GRID * GRID * GRID)      // 32768
#define BMIN  (-4.8f)
#define CELLH 0.3f
#define INVH  (1.0f / 0.3f)

#define FINF  __int_as_float(0x7f800000)
#define FNINF __int_as_float(0xff800000)

// ---- scratch (__device__ globals; zero-initialized at load) ----
__device__ float4 g_pts[NPTS];
__device__ int    g_pcell[NPTS];
__device__ int    g_cnt[NCELL];      // re-zeroed by k_scan each run (invariant)
__device__ int    g_off[NCELL + 4];
__device__ int    g_cur[NCELL];
__device__ float4 g_spts[NPTS];
__device__ int    g_idx[NPTS * KNN];
__device__ float  g_A1[NPTS * HDIM];
__device__ float  g_B1[NPTS * HDIM];
__device__ float  g_A2[NPTS * HDIM];
__device__ float  g_B2[NPTS * HDIM];
__device__ int    g_gmax[HDIM];      // re-zeroed by last gmax2 block (invariant)
__device__ int    g_tick;            // ticket; re-zeroed by last gmax2 block

__device__ __forceinline__ int cell_of(float v) {
    int c = (int)floorf((v - BMIN) * INVH);
    return min(max(c, 0), GRID - 1);
}

// ---------------------------------------------------------------------------
// K1: pack points, assign cells, histogram
__global__ void k_prep(const float* __restrict__ pos) {
    int i = blockIdx.x * blockDim.x + threadIdx.x;
    if (i >= NPTS) return;
    float x = pos[i * 3 + 0];
    float y = pos[i * 3 + 1];
    float z = pos[i * 3 + 2];
    g_pts[i] = make_float4(x, y, z, fmaf(z, z, fmaf(y, y, x * x)));
    int c = (cell_of(z) * GRID + cell_of(y)) * GRID + cell_of(x);
    g_pcell[i] = c;
    atomicAdd(&g_cnt[c], 1);
}

// ---------------------------------------------------------------------------
// K2: single-block scan over all 32768 cells (1024 thr x 32 cells each).
__global__ __launch_bounds__(1024) void k_scan() {
    __shared__ int s[1024];
    int t = threadIdx.x;
    int4 c[8];
    int sum = 0;
#pragma unroll
    for (int k = 0; k < 8; ++k) {
        c[k] = reinterpret_cast<const int4*>(g_cnt)[t * 8 + k];
        sum += c[k].x + c[k].y + c[k].z + c[k].w;
    }
    s[t] = sum;
    __syncthreads();
    for (int off = 1; off < 1024; off <<= 1) {
        int u = (t >= off) ? s[t - off] : 0;
        __syncthreads();
        s[t] += u;
        __syncthreads();
    }
    int run = s[t] - sum;   // exclusive base
#pragma unroll
    for (int k = 0; k < 8; ++k) {
        int4 cc = c[k];
        int4 o = make_int4(run, run + cc.x, run + cc.x + cc.y,
                           run + cc.x + cc.y + cc.z);
        reinterpret_cast<int4*>(g_off)[t * 8 + k] = o;
        reinterpret_cast<int4*>(g_cur)[t * 8 + k] = o;
        reinterpret_cast<int4*>(g_cnt)[t * 8 + k] = make_int4(0, 0, 0, 0);
        run += cc.x + cc.y + cc.z + cc.w;
    }
    if (t == 1023) g_off[NCELL] = NPTS;
}

// ---------------------------------------------------------------------------
// K3: scatter into cell-sorted order
__global__ void k_scatter() {
    int i = blockIdx.x * blockDim.x + threadIdx.x;
    if (i >= NPTS) return;
    int c = g_pcell[i];
    int slot = atomicAdd(&g_cur[c], 1);
    g_spts[slot] = g_pts[i];
}

// ---------------------------------------------------------------------------
// K4: exact kNN, TWO queries per warp (adjacent sorted slots share shells).
// Lanes 0-15: q0's sorted top-16; lanes 16-31: q1's. Every lane evaluates
// each candidate against BOTH queries. Expanding box around the pair's cell
// bounding-box; per-query exact stop bound vs scanned-box faces.
#define BITONIC32(D, J)                                                       \
    {                                                                         \
        _Pragma("unroll")                                                     \
        for (int k = 2; k <= 32; k <<= 1) {                                   \
            _Pragma("unroll")                                                 \
            for (int st = k >> 1; st > 0; st >>= 1) {                         \
                float od = __shfl_xor_sync(FULL, D, st);                      \
                int   oj = __shfl_xor_sync(FULL, J, st);                      \
                bool up = ((lane & k) == 0);                                  \
                bool lo = ((lane & st) == 0);                                 \
                bool keepMin = (lo == up);                                    \
                bool take = keepMin ? (od < D) : (od > D);                    \
                D = take ? od : D;                                            \
                J = take ? oj : J;                                            \
            }                                                                 \
        }                                                                     \
    }

// insert survivor (DW,JW) into q0's list (lanes 0-15)
#define INS_Q0(DW, JW)                                                        \
    {                                                                         \
        float pbd = __shfl_up_sync(FULL, bd, 1);                              \
        int   pbj = __shfl_up_sync(FULL, bj, 1);                              \
        if (lane < 16) {                                                      \
            bool ins  = (DW) < bd;                                            \
            bool pins = (lane > 0) && ((DW) < pbd);                           \
            bd = ins ? (pins ? pbd : (DW)) : bd;                              \
            bj = ins ? (pins ? pbj : (JW)) : bj;                              \
        }                                                                     \
    }
// insert survivor into q1's list (lanes 16-31)
#define INS_Q1(DW, JW)                                                        \
    {                                                                         \
        float pbd = __shfl_up_sync(FULL, bd, 1);                              \
        int   pbj = __shfl_up_sync(FULL, bj, 1);                              \
        if (lane >= 16) {                                                     \
            bool ins  = (DW) < bd;                                            \
            bool pins = (lane > 16) && ((DW) < pbd);                          \
            bd = ins ? (pins ? pbd : (DW)) : bd;                              \
            bj = ins ? (pins ? pbj : (JW)) : bj;                              \
        }                                                                     \
    }

// scan two segments [S00,S01), [S10,S11): lanes 0-15 seg0, 16-31 seg1;
// every lane computes distance of its candidate to BOTH queries.
#define SCANPAIR(S00, S01, S10, S11)                                          \
    {                                                                         \
        int mlo = (lane < 16) ? (S00) : (S10);                                \
        int mhi = (lane < 16) ? (S01) : (S11);                                \
        int sub = lane & 15;                                                  \
        for (int base = 0;; base += 16) {                                     \
            int j = mlo + base + sub;                                         \
            float d0 = FINF, d1 = FINF;                                       \
            if (j < mhi) {                                                    \
                float4 cd = __ldg(&g_spts[j]);                                \
                d0 = fmaf(ax0, cd.x, fmaf(ay0, cd.y,                          \
                     fmaf(az0, cd.z, cd.w + pw0)));                           \
                d1 = fmaf(ax1, cd.x, fmaf(ay1, cd.y,                          \
                     fmaf(az1, cd.z, cd.w + pw1)));                           \
            }                                                                 \
            if (first) {                                                      \
                first = false;                                                \
                float t0 = d0; int u0 = j;                                    \
                BITONIC32(t0, u0)                                             \
                float t1 = d1; int u1 = j;                                    \
                BITONIC32(t1, u1)                                             \
                float s1 = __shfl_xor_sync(FULL, t1, 16);                     \
                int  su1 = __shfl_xor_sync(FULL, u1, 16);                     \
                bd = (lane < 16) ? t0 : s1;                                   \
                bj = (lane < 16) ? u0 : su1;                                  \
                kth0 = __shfl_sync(FULL, bd, 15);                             \
                kth1 = __shfl_sync(FULL, bd, 31);                             \
            } else {                                                          \
                unsigned m0 = __ballot_sync(FULL, d0 < kth0);                 \
                if (m0) {                                                     \
                    do {                                                      \
                        int src = __ffs(m0) - 1; m0 &= m0 - 1;                \
                        float dw = __shfl_sync(FULL, d0, src);                \
                        int   jw = __shfl_sync(FULL, j, src);                 \
                        INS_Q0(dw, jw)                                        \
                    } while (m0);                                             \
                    kth0 = __shfl_sync(FULL, bd, 15);                         \
                }                                                             \
                unsigned m1 = __ballot_sync(FULL, d1 < kth1);                 \
                if (m1) {                                                     \
                    do {                                                      \
                        int src = __ffs(m1) - 1; m1 &= m1 - 1;                \
                        float dw = __shfl_sync(FULL, d1, src);                \
                        int   jw = __shfl_sync(FULL, j, src);                 \
                        INS_Q1(dw, jw)                                        \
                    } while (m1);                                             \
                    kth1 = __shfl_sync(FULL, bd, 31);                         \
                }                                                             \
            }                                                                 \
            unsigned more = __ballot_sync(FULL, mlo + base + 16 < mhi);       \
            if (!more) break;                                                 \
        }                                                                     \
    }

__global__ __launch_bounds__(128) void k_knng(const float* __restrict__ W1,
                                              const float* __restrict__ b1) {
    const unsigned FULL = 0xFFFFFFFFu;
    int pr = (blockIdx.x * 128 + threadIdx.x) >> 5;   // pair index
    int lane = threadIdx.x & 31;
    int q0 = pr * 2, q1 = q0 + 1;
    float4 p0 = g_spts[q0];
    float4 p1 = g_spts[q1];
    float pw0 = p0.w, pw1 = p1.w;
    float ax0 = -2.0f * p0.x, ay0 = -2.0f * p0.y, az0 = -2.0f * p0.z;
    float ax1 = -2.0f * p1.x, ay1 = -2.0f * p1.y, az1 = -2.0f * p1.z;
    int cx0 = cell_of(p0.x), cy0 = cell_of(p0.y), cz0 = cell_of(p0.z);
    int cx1 = cell_of(p1.x), cy1 = cell_of(p1.y), cz1 = cell_of(p1.z);
    int bx0 = min(cx0, cx1), bx1 = max(cx0, cx1);
    int by0 = min(cy0, cy1), by1 = max(cy0, cy1);
    int bz0 = min(cz0, cz1), bz1 = max(cz0, cz1);

    float bd = FINF;
    int   bj = 0;
    float kth0 = FINF, kth1 = FINF;
    bool  first = true;

    int pxlo = 1 << 30, pxhi = -(1 << 30);
    int pylo = 1 << 30, pyhi = -(1 << 30);
    int pzlo = 1 << 30, pzhi = -(1 << 30);

    for (int m = 1; m < 2 * GRID; ++m) {
        int zlo = max(bz0 - m, 0), zhi = min(bz1 + m, GRID - 1);
        int ylo = max(by0 - m, 0), yhi = min(by1 + m, GRID - 1);
        int xlo = max(bx0 - m, 0), xhi = min(bx1 + m, GRID - 1);
        int ny = yhi - ylo + 1;
        int nrows = (zhi - zlo + 1) * ny;
        // center row first on the very first shell (contains q0's own cell)
        int rc = (m == 1) ? ((cz0 - zlo) * ny + (cy0 - ylo)) : 0;

        for (int rbase = 0; rbase < nrows; rbase += 32) {
            int rid = rbase + lane;
            int a0 = 0, a1 = 0, b0 = 0, b1r = 0;
            if (rid < nrows) {
                int z = zlo + rid / ny;
                int y = ylo + rid - (rid / ny) * ny;
                int rb = (z * GRID + y) * GRID;
                bool newrow = (z < pzlo) | (z > pzhi) | (y < pylo) | (y > pyhi);
                if (newrow) {
                    a0 = __ldg(&g_off[rb + xlo]);
                    a1 = __ldg(&g_off[rb + xhi + 1]);
                } else {
                    if (pxlo > xlo) {
                        a0 = __ldg(&g_off[rb + xlo]);
                        a1 = __ldg(&g_off[rb + pxlo]);
                    }
                    if (pxhi < xhi) {
                        b0 = __ldg(&g_off[rb + pxhi + 1]);
                        b1r = __ldg(&g_off[rb + xhi + 1]);
                    }
                }
            }
            unsigned nA = __ballot_sync(FULL, (rid < nrows) && (a1 > a0));
            unsigned nB = __ballot_sync(FULL, (rid < nrows) && (b1r > b0));
            bool fp = (m == 1) && (rbase == 0) && ((nA >> rc) & 1u);
            while (nA | nB) {
                int r0, r1 = -1;
                bool f0 = false, f1 = false;
                if (fp) { r0 = rc; nA &= ~(1u << rc); fp = false; }
                else if (nA) { r0 = __ffs(nA) - 1; nA &= nA - 1; }
                else { r0 = __ffs(nB) - 1; f0 = true; nB &= nB - 1; }
                if (nA) { r1 = __ffs(nA) - 1; nA &= nA - 1; }
                else if (nB) { r1 = __ffs(nB) - 1; f1 = true; nB &= nB - 1; }
                int s00 = __shfl_sync(FULL, f0 ? b0 : a0, r0);
                int s01 = __shfl_sync(FULL, f0 ? b1r : a1, r0);
                int s10 = 0, s11 = 0;
                if (r1 >= 0) {
                    s10 = __shfl_sync(FULL, f1 ? b0 : a0, r1);
                    s11 = __shfl_sync(FULL, f1 ? b1r : a1, r1);
                }
                SCANPAIR(s00, s01, s10, s11)
            }
        }

        // per-query exact stop: distance to scanned-box faces (INF at edges)
        float e0x = (xlo > 0)        ? (p0.x - (BMIN + (float)xlo * CELLH))       : FINF;
        float e1x = (xhi < GRID - 1) ? ((BMIN + (float)(xhi + 1) * CELLH) - p0.x) : FINF;
        float e0y = (ylo > 0)        ? (p0.y - (BMIN + (float)ylo * CELLH))       : FINF;
        float e1y = (yhi < GRID - 1) ? ((BMIN + (float)(yhi + 1) * CELLH) - p0.y) : FINF;
        float e0z = (zlo > 0)        ? (p0.z - (BMIN + (float)zlo * CELLH))       : FINF;
        float e1z = (zhi < GRID - 1) ? ((BMIN + (float)(zhi + 1) * CELLH) - p0.z) : FINF;
        float bb0 = fminf(fminf(fminf(e0x, e1x), fminf(e0y, e1y)), fminf(e0z, e1z)) - 1e-4f;
        float g0x = (xlo > 0)        ? (p1.x - (BMIN + (float)xlo * CELLH))       : FINF;
        float g1x = (xhi < GRID - 1) ? ((BMIN + (float)(xhi + 1) * CELLH) - p1.x) : FINF;
        float g0y = (ylo > 0)        ? (p1.y - (BMIN + (float)ylo * CELLH))       : FINF;
        float g1y = (yhi < GRID - 1) ? ((BMIN + (float)(yhi + 1) * CELLH) - p1.y) : FINF;
        float g0z = (zlo > 0)        ? (p1.z - (BMIN + (float)zlo * CELLH))       : FINF;
        float g1z = (zhi < GRID - 1) ? ((BMIN + (float)(zhi + 1) * CELLH) - p1.z) : FINF;
        float bb1 = fminf(fminf(fminf(g0x, g1x), fminf(g0y, g1y)), fminf(g0z, g1z)) - 1e-4f;

        pxlo = xlo; pxhi = xhi; pylo = ylo; pyhi = yhi; pzlo = zlo; pzhi = zhi;
        if ((kth0 <= bb0 * bb0) && (kth1 <= bb1 * bb1)) break;
    }

    if (lane < KNN) g_idx[q0 * KNN + lane] = bj;
    else            g_idx[q1 * KNN + (lane - KNN)] = bj;

    // Fused layer-1 projections for both queries: 2 h-columns per lane each.
#pragma unroll
    for (int hh = 0; hh < 2; ++hh) {
        int h = lane + hh * 32;
        float wa0 = __ldg(&W1[0 * HDIM + h]);
        float wa1 = __ldg(&W1[1 * HDIM + h]);
        float wa2 = __ldg(&W1[2 * HDIM + h]);
        float wb0 = __ldg(&W1[3 * HDIM + h]);
        float wb1 = __ldg(&W1[4 * HDIM + h]);
        float wb2 = __ldg(&W1[5 * HDIM + h]);
        float bh = __ldg(&b1[h]);
        float v0 = fmaf(p0.x, wb0, fmaf(p0.y, wb1, p0.z * wb2));
        float u0 = fmaf(p0.x, wa0 - wb0, fmaf(p0.y, wa1 - wb1, p0.z * (wa2 - wb2))) + bh;
        g_A1[q0 * HDIM + h] = u0;
        g_B1[q0 * HDIM + h] = v0;
        float v1 = fmaf(p1.x, wb0, fmaf(p1.y, wb1, p1.z * wb2));
        float u1 = fmaf(p1.x, wa0 - wb0, fmaf(p1.y, wa1 - wb1, p1.z * (wa2 - wb2))) + bh;
        g_A1[q1 * HDIM + h] = u1;
        g_B1[q1 * HDIM + h] = v1;
    }
}

// ---------------------------------------------------------------------------
// K5: fused gmax1 + layer-2 projections.
__global__ __launch_bounds__(256) void k_feat2(const float* __restrict__ W2,
                                               const float* __restrict__ b2) {
    __shared__ float sWu[HDIM * HDIM];
    __shared__ float sWv[HDIM * HDIM];
    __shared__ float sX[64 * HDIM];
    int tid = threadIdx.x;
    for (int e = tid; e < 64 * 16; e += 256) {
        int i = blockIdx.x * 64 + (e >> 4);
        int q = e & 15;
        const int4* row = reinterpret_cast<const int4*>(g_idx + i * KNN);
        float4 mx = make_float4(FNINF, FNINF, FNINF, FNINF);
#pragma unroll
        for (int k4 = 0; k4 < 4; ++k4) {
            int4 jj = __ldg(row + k4);
            int js[4] = {jj.x, jj.y, jj.z, jj.w};
#pragma unroll
            for (int e4 = 0; e4 < 4; ++e4) {
                float4 v = reinterpret_cast<const float4*>(g_B1)[js[e4] * 16 + q];
                mx.x = fmaxf(mx.x, v.x); mx.y = fmaxf(mx.y, v.y);
                mx.z = fmaxf(mx.z, v.z); mx.w = fmaxf(mx.w, v.w);
            }
        }
        float4 a = reinterpret_cast<const float4*>(g_A1)[i * 16 + q];
        float4 o;
        o.x = fmaxf(a.x + mx.x, 0.0f); o.y = fmaxf(a.y + mx.y, 0.0f);
        o.z = fmaxf(a.z + mx.z, 0.0f); o.w = fmaxf(a.w + mx.w, 0.0f);
        reinterpret_cast<float4*>(sX)[e] = o;
    }
    for (int e = tid; e < HDIM * HDIM; e += 256) {
        int j = e >> 6, h = e & 63;
        float wb = W2[(j + HDIM) * HDIM + h];
        sWv[e] = wb;
        sWu[e] = W2[j * HDIM + h] - wb;
    }
    __syncthreads();

    int ty = tid >> 4, q = tid & 15;
    float4 au[4], av[4];
#pragma unroll
    for (int k = 0; k < 4; ++k) {
        au[k] = make_float4(0.f, 0.f, 0.f, 0.f);
        av[k] = make_float4(0.f, 0.f, 0.f, 0.f);
    }
#pragma unroll 4
    for (int j = 0; j < HDIM; ++j) {
        float4 wu = reinterpret_cast<const float4*>(sWu)[j * 16 + q];
        float4 wv = reinterpret_cast<const float4*>(sWv)[j * 16 + q];
#pragma unroll
        for (int k = 0; k < 4; ++k) {
            float xj = sX[(ty * 4 + k) * HDIM + j];
            au[k].x = fmaf(xj, wu.x, au[k].x); au[k].y = fmaf(xj, wu.y, au[k].y);
            au[k].z = fmaf(xj, wu.z, au[k].z); au[k].w = fmaf(xj, wu.w, au[k].w);
            av[k].x = fmaf(xj, wv.x, av[k].x); av[k].y = fmaf(xj, wv.y, av[k].y);
            av[k].z = fmaf(xj, wv.z, av[k].z); av[k].w = fmaf(xj, wv.w, av[k].w);
        }
    }
    float4 bb = reinterpret_cast<const float4*>(b2)[q];
#pragma unroll
    for (int k = 0; k < 4; ++k) {
        int i = blockIdx.x * 64 + ty * 4 + k;
        au[k].x += bb.x; au[k].y += bb.y; au[k].z += bb.z; au[k].w += bb.w;
        reinterpret_cast<float4*>(g_A2)[i * 16 + q] = au[k];
        reinterpret_cast<float4*>(g_B2)[i * 16 + q] = av[k];
    }
}

// ---------------------------------------------------------------------------
// K6: h2 = relu(A2 + max_k B2[idx]) -> global max -> (last block) output.
__global__ __launch_bounds__(256) void k_gmax2(const float* __restrict__ Wc,
                                               const float* __restrict__ bc,
                                               float* __restrict__ out,
                                               int nblocks) {
    __shared__ int sg[HDIM];
    __shared__ bool amLast;
    if (threadIdx.x < HDIM) sg[threadIdx.x] = 0;
    __syncthreads();
    int gt = blockIdx.x * 256 + threadIdx.x;
    int i = gt >> 4, q = gt & 15;
    const int4* row = reinterpret_cast<const int4*>(g_idx + i * KNN);
    float4 m = make_float4(FNINF, FNINF, FNINF, FNINF);
#pragma unroll
    for (int k4 = 0; k4 < 4; ++k4) {
        int4 jj = __ldg(row + k4);
        int js[4] = {jj.x, jj.y, jj.z, jj.w};
#pragma unroll
        for (int e = 0; e < 4; ++e) {
            float4 v = reinterpret_cast<const float4*>(g_B2)[js[e] * 16 + q];
            m.x = fmaxf(m.x, v.x); m.y = fmaxf(m.y, v.y);
            m.z = fmaxf(m.z, v.z); m.w = fmaxf(m.w, v.w);
        }
    }
    float4 a = reinterpret_cast<const float4*>(g_A2)[i * 16 + q];
    float4 o;
    o.x = fmaxf(a.x + m.x, 0.0f); o.y = fmaxf(a.y + m.y, 0.0f);
    o.z = fmaxf(a.z + m.z, 0.0f); o.w = fmaxf(a.w + m.w, 0.0f);
    atomicMax(&sg[q * 4 + 0], __float_as_int(o.x));
    atomicMax(&sg[q * 4 + 1], __float_as_int(o.y));
    atomicMax(&sg[q * 4 + 2], __float_as_int(o.z));
    atomicMax(&sg[q * 4 + 3], __float_as_int(o.w));
    __syncthreads();
    if (threadIdx.x < HDIM) atomicMax(&g_gmax[threadIdx.x], sg[threadIdx.x]);

    __threadfence();
    if (threadIdx.x == 0) {
        int t = atomicAdd(&g_tick, 1);
        amLast = (t == nblocks - 1);
    }
    __syncthreads();
    if (amLast) {
        __shared__ float gv[HDIM];
        int c = threadIdx.x;
        if (c < HDIM) gv[c] = __int_as_float(atomicAdd(&g_gmax[c], 0));
        __syncthreads();
        if (c < CDIM) {
            float acc = bc[c];
#pragma unroll
            for (int h = 0; h < HDIM; ++h)
                acc = fmaf(gv[h], Wc[h * CDIM + c], acc);
            out[c] = acc;
        }
        if (c < HDIM) g_gmax[c] = 0;
        if (c == 0) g_tick = 0;
    }
}

// ---------------------------------------------------------------------------
extern "C" void kernel_launch(void* const* d_in, const int* in_sizes, int n_in,
                              void* d_out, int out_size) {
    const float* pos = (const float*)d_in[0];
    // d_in[1] = batch (all zeros, num_segments=1) -> unused
    const float* W1 = (const float*)d_in[2];
    const float* b1 = (const float*)d_in[3];
    const float* W2 = (const float*)d_in[4];
    const float* b2 = (const float*)d_in[5];
    const float* Wc = (const float*)d_in[6];
    const float* bc = (const float*)d_in[7];
    float* out = (float*)d_out;

    k_prep<<<NPTS / 256, 256>>>(pos);                         // 0
    k_scan<<<1, 1024>>>();                                    // 1
    k_scatter<<<NPTS / 256, 256>>>();                         // 2
    k_knng<<<NPTS * 16 / 128, 128>>>(W1, b1);                 // 3  <- ncu slot
    k_feat2<<<NPTS / 64, 256>>>(W2, b2);                      // 4
    k_gmax2<<<NPTS * 16 / 256, 256>>>(Wc, bc, out,
                                      NPTS * 16 / 256);       // 5
}

// round 13
// speedup vs baseline: 2.9230x; 2.9230x over previous
#include <cuda_runtime.h>

// Problem constants
#define NPTS 16384
#define KNN  16
#define HDIM 64
#define CDIM 10

// Spatial grid: h=0.3 over [-4.8, 4.8]^3
#define GRID  32
#define NCELL (GRID * GRID * GRID)      // 32768
#define BMIN  (-4.8f)
#define CELLH 0.3f
#define INVH  (1.0f / 0.3f)

#define FINF  __int_as_float(0x7f800000)
#define FNINF __int_as_float(0xff800000)

// ---- scratch (__device__ globals; zero-initialized at load) ----
__device__ float4 g_pts[NPTS];
__device__ int    g_pcell[NPTS];
__device__ int    g_cnt[NCELL];      // re-zeroed by k_scan each run (invariant)
__device__ int    g_off[NCELL + 4];
__device__ int    g_cur[NCELL];
__device__ float4 g_spts[NPTS];
__device__ int    g_idx[NPTS * KNN];
__device__ float  g_A1[NPTS * HDIM];
__device__ float  g_B1[NPTS * HDIM];
__device__ float  g_A2[NPTS * HDIM];
__device__ float  g_B2[NPTS * HDIM];
__device__ int    g_gmax[HDIM];      // re-zeroed by last gmax2 block (invariant)
__device__ int    g_tick;            // ticket; re-zeroed by last gmax2 block

__device__ __forceinline__ int cell_of(float v) {
    int c = (int)floorf((v - BMIN) * INVH);
    return min(max(c, 0), GRID - 1);
}

// ---------------------------------------------------------------------------
// K1: pack points, assign cells, histogram
__global__ void k_prep(const float* __restrict__ pos) {
    int i = blockIdx.x * blockDim.x + threadIdx.x;
    if (i >= NPTS) return;
    float x = pos[i * 3 + 0];
    float y = pos[i * 3 + 1];
    float z = pos[i * 3 + 2];
    g_pts[i] = make_float4(x, y, z, fmaf(z, z, fmaf(y, y, x * x)));
    int c = (cell_of(z) * GRID + cell_of(y)) * GRID + cell_of(x);
    g_pcell[i] = c;
    atomicAdd(&g_cnt[c], 1);
}

// ---------------------------------------------------------------------------
// K2: single-block scan over all 32768 cells (1024 thr x 32 cells each).
__global__ __launch_bounds__(1024) void k_scan() {
    __shared__ int s[1024];
    int t = threadIdx.x;
    int4 c[8];
    int sum = 0;
#pragma unroll
    for (int k = 0; k < 8; ++k) {
        c[k] = reinterpret_cast<const int4*>(g_cnt)[t * 8 + k];
        sum += c[k].x + c[k].y + c[k].z + c[k].w;
    }
    s[t] = sum;
    __syncthreads();
    for (int off = 1; off < 1024; off <<= 1) {
        int u = (t >= off) ? s[t - off] : 0;
        __syncthreads();
        s[t] += u;
        __syncthreads();
    }
    int run = s[t] - sum;   // exclusive base
#pragma unroll
    for (int k = 0; k < 8; ++k) {
        int4 cc = c[k];
        int4 o = make_int4(run, run + cc.x, run + cc.x + cc.y,
                           run + cc.x + cc.y + cc.z);
        reinterpret_cast<int4*>(g_off)[t * 8 + k] = o;
        reinterpret_cast<int4*>(g_cur)[t * 8 + k] = o;
        reinterpret_cast<int4*>(g_cnt)[t * 8 + k] = make_int4(0, 0, 0, 0);
        run += cc.x + cc.y + cc.z + cc.w;
    }
    if (t == 1023) g_off[NCELL] = NPTS;
}

// ---------------------------------------------------------------------------
// K3: scatter into cell-sorted order
__global__ void k_scatter() {
    int i = blockIdx.x * blockDim.x + threadIdx.x;
    if (i >= NPTS) return;
    int c = g_pcell[i];
    int slot = atomicAdd(&g_cur[c], 1);
    g_spts[slot] = g_pts[i];
}

// ---------------------------------------------------------------------------
// K4: exact kNN (one warp/query) + fused feat1 epilogue.  [R11 structure]
// DUAL-SEGMENT tiles: two row segments per iteration, half-warp each.
// Uniform trip count (segment bounds are warp-uniform) -> no per-iter ballot.
#define BITONIC32(D, J)                                                       \
    {                                                                         \
        _Pragma("unroll")                                                     \
        for (int k = 2; k <= 32; k <<= 1) {                                   \
            _Pragma("unroll")                                                 \
            for (int st = k >> 1; st > 0; st >>= 1) {                         \
                float od = __shfl_xor_sync(FULL, D, st);                      \
                int   oj = __shfl_xor_sync(FULL, J, st);                      \
                bool up = ((lane & k) == 0);                                  \
                bool lo = ((lane & st) == 0);                                 \
                bool keepMin = (lo == up);                                    \
                bool take = keepMin ? (od < D) : (od > D);                    \
                D = take ? od : D;                                            \
                J = take ? oj : J;                                            \
            }                                                                 \
        }                                                                     \
    }

#define SCANPAIR(S00, S01, S10, S11)                                          \
    {                                                                         \
        int mlo = (lane < 16) ? (S00) : (S10);                                \
        int mhi = (lane < 16) ? (S01) : (S11);                                \
        int sub = lane & 15;                                                  \
        int it0 = ((S01) - (S00) + 15) >> 4;                                  \
        int it1 = ((S11) - (S10) + 15) >> 4;                                  \
        int iters = max(it0, it1);                                            \
        for (int it = 0; it < iters; ++it) {                                  \
            int j = mlo + it * 16 + sub;                                      \
            float d = FINF;                                                   \
            if (j < mhi) {                                                    \
                float4 cd = __ldg(&g_spts[j]);                                \
                d = fmaf(ax, cd.x, fmaf(ay, cd.y, fmaf(az, cd.z, cd.w + pw)));\
            }                                                                 \
            if (first) {                                                      \
                first = false;                                                \
                BITONIC32(d, j)                                               \
                bd = d; bj = j;                                               \
                kth = __shfl_sync(FULL, bd, KNN - 1);                         \
            } else {                                                          \
                unsigned msk = __ballot_sync(FULL, d < kth);                  \
                if (msk) {                                                    \
                    do {                                                      \
                        int src = __ffs(msk) - 1;                             \
                        msk &= msk - 1;                                       \
                        float dw = __shfl_sync(FULL, d, src);                 \
                        int   jw = __shfl_sync(FULL, j, src);                 \
                        float pbd = __shfl_up_sync(FULL, bd, 1);              \
                        int   pbj = __shfl_up_sync(FULL, bj, 1);              \
                        bool ins  = dw < bd;                                  \
                        bool pins = (lane > 0) && (dw < pbd);                 \
                        bd = ins ? (pins ? pbd : dw) : bd;                    \
                        bj = ins ? (pins ? pbj : jw) : bj;                    \
                    } while (msk);                                            \
                    kth = __shfl_sync(FULL, bd, KNN - 1);                     \
                }                                                             \
            }                                                                 \
        }                                                                     \
    }

__global__ __launch_bounds__(128) void k_knng(const float* __restrict__ W1,
                                              const float* __restrict__ b1) {
    const unsigned FULL = 0xFFFFFFFFu;
    int warp = (blockIdx.x * 128 + threadIdx.x) >> 5;
    int lane = threadIdx.x & 31;
    float4 p = g_spts[warp];
    float pw = p.w;
    float ax = -2.0f * p.x, ay = -2.0f * p.y, az = -2.0f * p.z;
    int cx = cell_of(p.x), cy = cell_of(p.y), cz = cell_of(p.z);

    float bd = FINF;   // lane l: l-th smallest distance so far (32-deep list)
    int   bj = 0;
    float kth = FINF;  // warp-uniform (stale-safe) 16th best
    bool  first = true;

    for (int m = 1; m < GRID; ++m) {
        int zlo = max(cz - m, 0), zhi = min(cz + m, GRID - 1);
        int ylo = max(cy - m, 0), yhi = min(cy + m, GRID - 1);
        int xlo = max(cx - m, 0), xhi = min(cx + m, GRID - 1);
        int ny = yhi - ylo + 1;
        int nrows = (zhi - zlo + 1) * ny;
        int rc = (m == 1) ? ((cz - zlo) * ny + (cy - ylo)) : 0;

        for (int rbase = 0; rbase < nrows; rbase += 32) {
            int rid = rbase + lane;
            int a0 = 0, a1 = 0, b0 = 0, b1r = 0;
            if (rid < nrows) {
                int z = zlo + rid / ny;
                int y = ylo + rid - (rid / ny) * ny;
                int rb = (z * GRID + y) * GRID;
                bool fullrow = (m == 1) || (abs(z - cz) == m) || (abs(y - cy) == m);
                if (fullrow) {
                    a0 = __ldg(&g_off[rb + xlo]);
                    a1 = __ldg(&g_off[rb + xhi + 1]);
                } else {
                    if (cx - m >= 0) {
                        a0 = __ldg(&g_off[rb + cx - m]);
                        a1 = __ldg(&g_off[rb + cx - m + 1]);
                    }
                    if (cx + m < GRID) {
                        b0 = __ldg(&g_off[rb + cx + m]);
                        b1r = __ldg(&g_off[rb + cx + m + 1]);
                    }
                }
            }
            unsigned nA = __ballot_sync(FULL, (rid < nrows) && (a1 > a0));
            unsigned nB = __ballot_sync(FULL, (rid < nrows) && (b1r > b0));
            bool fp = (m == 1) && (rbase == 0) && ((nA >> rc) & 1u);
            while (nA | nB) {
                int r0, r1 = -1;
                bool f0 = false, f1 = false;
                if (fp) { r0 = rc; nA &= ~(1u << rc); fp = false; }
                else if (nA) { r0 = __ffs(nA) - 1; nA &= nA - 1; }
                else { r0 = __ffs(nB) - 1; f0 = true; nB &= nB - 1; }
                if (nA) { r1 = __ffs(nA) - 1; nA &= nA - 1; }
                else if (nB) { r1 = __ffs(nB) - 1; f1 = true; nB &= nB - 1; }
                int s00 = __shfl_sync(FULL, f0 ? b0 : a0, r0);
                int s01 = __shfl_sync(FULL, f0 ? b1r : a1, r0);
                int s10 = 0, s11 = 0;
                if (r1 >= 0) {
                    s10 = __shfl_sync(FULL, f1 ? b0 : a0, r1);
                    s11 = __shfl_sync(FULL, f1 ? b1r : a1, r1);
                }
                SCANPAIR(s00, s01, s10, s11)
            }
        }

        float f0 = (xlo > 0)        ? (p.x - (BMIN + (float)xlo * CELLH))       : FINF;
        float f1 = (xhi < GRID - 1) ? ((BMIN + (float)(xhi + 1) * CELLH) - p.x) : FINF;
        float f2 = (ylo > 0)        ? (p.y - (BMIN + (float)ylo * CELLH))       : FINF;
        float f3 = (yhi < GRID - 1) ? ((BMIN + (float)(yhi + 1) * CELLH) - p.y) : FINF;
        float f4 = (zlo > 0)        ? (p.z - (BMIN + (float)zlo * CELLH))       : FINF;
        float f5 = (zhi < GRID - 1) ? ((BMIN + (float)(zhi + 1) * CELLH) - p.z) : FINF;
        float bb = fminf(fminf(fminf(f0, f1), fminf(f2, f3)), fminf(f4, f5));
        bb -= 1e-4f;  // fp slack on face positions
        if (kth <= bb * bb) break;
    }
    if (lane < KNN) g_idx[warp * KNN + lane] = bj;

    // Fused layer-1 projections for this query: 2 h-columns per lane.
#pragma unroll
    for (int hh = 0; hh < 2; ++hh) {
        int h = lane + hh * 32;
        float wa0 = __ldg(&W1[0 * HDIM + h]);
        float wa1 = __ldg(&W1[1 * HDIM + h]);
        float wa2 = __ldg(&W1[2 * HDIM + h]);
        float wb0 = __ldg(&W1[3 * HDIM + h]);
        float wb1 = __ldg(&W1[4 * HDIM + h]);
        float wb2 = __ldg(&W1[5 * HDIM + h]);
        float v = fmaf(p.x, wb0, fmaf(p.y, wb1, p.z * wb2));
        float u = fmaf(p.x, wa0 - wb0, fmaf(p.y, wa1 - wb1, p.z * (wa2 - wb2)))
                  + __ldg(&b1[h]);
        g_A1[warp * HDIM + h] = u;
        g_B1[warp * HDIM + h] = v;
    }
}

// ---------------------------------------------------------------------------
// K5: fused gmax1 + layer-2 projections.
__global__ __launch_bounds__(256) void k_feat2(const float* __restrict__ W2,
                                               const float* __restrict__ b2) {
    __shared__ float sWu[HDIM * HDIM];
    __shared__ float sWv[HDIM * HDIM];
    __shared__ float sX[64 * HDIM];
    int tid = threadIdx.x;
    for (int e = tid; e < 64 * 16; e += 256) {
        int i = blockIdx.x * 64 + (e >> 4);
        int q = e & 15;
        const int4* row = reinterpret_cast<const int4*>(g_idx + i * KNN);
        float4 mx = make_float4(FNINF, FNINF, FNINF, FNINF);
#pragma unroll
        for (int k4 = 0; k4 < 4; ++k4) {
            int4 jj = __ldg(row + k4);
            int js[4] = {jj.x, jj.y, jj.z, jj.w};
#pragma unroll
            for (int e4 = 0; e4 < 4; ++e4) {
                float4 v = reinterpret_cast<const float4*>(g_B1)[js[e4] * 16 + q];
                mx.x = fmaxf(mx.x, v.x); mx.y = fmaxf(mx.y, v.y);
                mx.z = fmaxf(mx.z, v.z); mx.w = fmaxf(mx.w, v.w);
            }
        }
        float4 a = reinterpret_cast<const float4*>(g_A1)[i * 16 + q];
        float4 o;
        o.x = fmaxf(a.x + mx.x, 0.0f); o.y = fmaxf(a.y + mx.y, 0.0f);
        o.z = fmaxf(a.z + mx.z, 0.0f); o.w = fmaxf(a.w + mx.w, 0.0f);
        reinterpret_cast<float4*>(sX)[e] = o;
    }
    for (int e = tid; e < HDIM * HDIM; e += 256) {
        int j = e >> 6, h = e & 63;
        float wb = W2[(j + HDIM) * HDIM + h];
        sWv[e] = wb;
        sWu[e] = W2[j * HDIM + h] - wb;
    }
    __syncthreads();

    int ty = tid >> 4, q = tid & 15;
    float4 au[4], av[4];
#pragma unroll
    for (int k = 0; k < 4; ++k) {
        au[k] = make_float4(0.f, 0.f, 0.f, 0.f);
        av[k] = make_float4(0.f, 0.f, 0.f, 0.f);
    }
#pragma unroll 4
    for (int j = 0; j < HDIM; ++j) {
        float4 wu = reinterpret_cast<const float4*>(sWu)[j * 16 + q];
        float4 wv = reinterpret_cast<const float4*>(sWv)[j * 16 + q];
#pragma unroll
        for (int k = 0; k < 4; ++k) {
            float xj = sX[(ty * 4 + k) * HDIM + j];
            au[k].x = fmaf(xj, wu.x, au[k].x); au[k].y = fmaf(xj, wu.y, au[k].y);
            au[k].z = fmaf(xj, wu.z, au[k].z); au[k].w = fmaf(xj, wu.w, au[k].w);
            av[k].x = fmaf(xj, wv.x, av[k].x); av[k].y = fmaf(xj, wv.y, av[k].y);
            av[k].z = fmaf(xj, wv.z, av[k].z); av[k].w = fmaf(xj, wv.w, av[k].w);
        }
    }
    float4 bb = reinterpret_cast<const float4*>(b2)[q];
#pragma unroll
    for (int k = 0; k < 4; ++k) {
        int i = blockIdx.x * 64 + ty * 4 + k;
        au[k].x += bb.x; au[k].y += bb.y; au[k].z += bb.z; au[k].w += bb.w;
        reinterpret_cast<float4*>(g_A2)[i * 16 + q] = au[k];
        reinterpret_cast<float4*>(g_B2)[i * 16 + q] = av[k];
    }
}

// ---------------------------------------------------------------------------
// K6: h2 = relu(A2 + max_k B2[idx]) -> global max -> (last block) output.
__global__ __launch_bounds__(256) void k_gmax2(const float* __restrict__ Wc,
                                               const float* __restrict__ bc,
                                               float* __restrict__ out,
                                               int nblocks) {
    __shared__ int sg[HDIM];
    __shared__ bool amLast;
    if (threadIdx.x < HDIM) sg[threadIdx.x] = 0;
    __syncthreads();
    int gt = blockIdx.x * 256 + threadIdx.x;
    int i = gt >> 4, q = gt & 15;
    const int4* row = reinterpret_cast<const int4*>(g_idx + i * KNN);
    float4 m = make_float4(FNINF, FNINF, FNINF, FNINF);
#pragma unroll
    for (int k4 = 0; k4 < 4; ++k4) {
        int4 jj = __ldg(row + k4);
        int js[4] = {jj.x, jj.y, jj.z, jj.w};
#pragma unroll
        for (int e = 0; e < 4; ++e) {
            float4 v = reinterpret_cast<const float4*>(g_B2)[js[e] * 16 + q];
            m.x = fmaxf(m.x, v.x); m.y = fmaxf(m.y, v.y);
            m.z = fmaxf(m.z, v.z); m.w = fmaxf(m.w, v.w);
        }
    }
    float4 a = reinterpret_cast<const float4*>(g_A2)[i * 16 + q];
    float4 o;
    o.x = fmaxf(a.x + m.x, 0.0f); o.y = fmaxf(a.y + m.y, 0.0f);
    o.z = fmaxf(a.z + m.z, 0.0f); o.w = fmaxf(a.w + m.w, 0.0f);
    atomicMax(&sg[q * 4 + 0], __float_as_int(o.x));
    atomicMax(&sg[q * 4 + 1], __float_as_int(o.y));
    atomicMax(&sg[q * 4 + 2], __float_as_int(o.z));
    atomicMax(&sg[q * 4 + 3], __float_as_int(o.w));
    __syncthreads();
    if (threadIdx.x < HDIM) atomicMax(&g_gmax[threadIdx.x], sg[threadIdx.x]);

    __threadfence();
    if (threadIdx.x == 0) {
        int t = atomicAdd(&g_tick, 1);
        amLast = (t == nblocks - 1);
    }
    __syncthreads();
    if (amLast) {
        __shared__ float gv[HDIM];
        int c = threadIdx.x;
        if (c < HDIM) gv[c] = __int_as_float(atomicAdd(&g_gmax[c], 0));
        __syncthreads();
        if (c < CDIM) {
            float acc = bc[c];
#pragma unroll
            for (int h = 0; h < HDIM; ++h)
                acc = fmaf(gv[h], Wc[h * CDIM + c], acc);
            out[c] = acc;
        }
        if (c < HDIM) g_gmax[c] = 0;
        if (c == 0) g_tick = 0;
    }
}

// ---------------------------------------------------------------------------
extern "C" void kernel_launch(void* const* d_in, const int* in_sizes, int n_in,
                              void* d_out, int out_size) {
    const float* pos = (const float*)d_in[0];
    // d_in[1] = batch (all zeros, num_segments=1) -> unused
    const float* W1 = (const float*)d_in[2];
    const float* b1 = (const float*)d_in[3];
    const float* W2 = (const float*)d_in[4];
    const float* b2 = (const float*)d_in[5];
    const float* Wc = (const float*)d_in[6];
    const float* bc = (const float*)d_in[7];
    float* out = (float*)d_out;

    k_prep<<<NPTS / 256, 256>>>(pos);                         // 0
    k_scan<<<1, 1024>>>();                                    // 1
    k_scatter<<<NPTS / 256, 256>>>();                         // 2
    k_knng<<<NPTS * 32 / 128, 128>>>(W1, b1);                 // 3  <- ncu slot
    k_feat2<<<NPTS / 64, 256>>>(W2, b2);                      // 4
    k_gmax2<<<NPTS * 16 / 256, 256>>>(Wc, bc, out,
                                      NPTS * 16 / 256);       // 5
}

// round 14
// speedup vs baseline: 3.3376x; 1.1418x over previous
#include <cuda_runtime.h>

// Problem constants
#define NPTS 16384
#define KNN  16
#define HDIM 64
#define CDIM 10

// Spatial grid: h=0.3 over [-4.8, 4.8]^3
#define GRID  32
#define NCELL (GRID * GRID * GRID)      // 32768
#define BMIN  (-4.8f)
#define CELLH 0.3f
#define INVH  (1.0f / 0.3f)

#define FINF  __int_as_float(0x7f800000)
#define FNINF __int_as_float(0xff800000)

// ---- scratch (__device__ globals; zero-initialized at load) ----
__device__ int    g_pcell_unused[1];
__device__ int    g_cnt[NCELL];      // re-zeroed inside k_build each run
__device__ int    g_off[NCELL + 4];
__device__ int    g_cur[NCELL];
__device__ int    g_bsum[64];
__device__ float4 g_spts[NPTS];
__device__ int    g_idx[NPTS * KNN];
__device__ float  g_A1[NPTS * HDIM];
__device__ float  g_B1[NPTS * HDIM];
__device__ float  g_A2[NPTS * HDIM];
__device__ float  g_B2[NPTS * HDIM];
__device__ int    g_gmax[HDIM];      // re-zeroed by last gmax2 block
__device__ int    g_tick;            // ticket; re-zeroed by last gmax2 block
__device__ int    g_sy1, g_sy2, g_sy3, g_dn;   // k_build barriers (self-reset)

__device__ __forceinline__ int cell_of(float v) {
    int c = (int)floorf((v - BMIN) * INVH);
    return min(max(c, 0), GRID - 1);
}

// software grid barrier for a co-resident 64-block grid
__device__ __forceinline__ void gbar64(int* ctr) {
    __syncthreads();
    if (threadIdx.x == 0) {
        __threadfence();
        atomicAdd(ctr, 1);
        while (atomicAdd(ctr, 0) < 64) { }
    }
    __syncthreads();
}

// ---------------------------------------------------------------------------
// K1: fused prep + histogram + scan + scatter. 64 blocks x 256 threads,
// all co-resident -> software grid barriers are safe. Counters self-reset.
__global__ __launch_bounds__(256) void k_build(const float* __restrict__ pos) {
    __shared__ int s[256];
    __shared__ int sb[64];
    int t = threadIdx.x, b = blockIdx.x;

    // phase 1: pack point, histogram cell
    int i = b * 256 + t;
    float x = pos[i * 3 + 0];
    float y = pos[i * 3 + 1];
    float z = pos[i * 3 + 2];
    float w = fmaf(z, z, fmaf(y, y, x * x));
    int c = (cell_of(z) * GRID + cell_of(y)) * GRID + cell_of(x);
    atomicAdd(&g_cnt[c], 1);
    gbar64(&g_sy1);

    // phase 2a: per-block chunk sums (128 int4 = 512 cells per block)
    int4 cc = make_int4(0, 0, 0, 0);
    int sum = 0;
    if (t < 128) {
        cc = reinterpret_cast<const int4*>(g_cnt)[b * 128 + t];
        sum = cc.x + cc.y + cc.z + cc.w;
    }
    s[t] = sum;
    __syncthreads();
    for (int off = 1; off < 256; off <<= 1) {
        int u = (t >= off) ? s[t - off] : 0;
        __syncthreads();
        s[t] += u;
        __syncthreads();
    }
    int excl = s[t] - sum;
    if (t == 255) g_bsum[b] = s[255];
    gbar64(&g_sy2);

    // phase 2b: block base via scan of 64 chunk sums; write offsets
    if (t < 64) sb[t] = g_bsum[t];
    __syncthreads();
    if (t == 0) {
        int r = 0;
        for (int k = 0; k < 64; ++k) { int v = sb[k]; sb[k] = r; r += v; }
    }
    __syncthreads();
    int base = sb[b] + excl;
    if (t < 128) {
        int4 o = make_int4(base, base + cc.x, base + cc.x + cc.y,
                           base + cc.x + cc.y + cc.z);
        reinterpret_cast<int4*>(g_off)[b * 128 + t] = o;
        reinterpret_cast<int4*>(g_cur)[b * 128 + t] = o;
        reinterpret_cast<int4*>(g_cnt)[b * 128 + t] = make_int4(0, 0, 0, 0);
    }
    if (b == 63 && t == 255) g_off[NCELL] = NPTS;
    gbar64(&g_sy3);

    // phase 3: scatter (point still in registers)
    int slot = atomicAdd(&g_cur[c], 1);
    g_spts[slot] = make_float4(x, y, z, w);

    // reset barrier counters for next graph replay
    __syncthreads();
    if (t == 0) {
        __threadfence();
        int d = atomicAdd(&g_dn, 1);
        if (d == 63) {
            atomicExch(&g_sy1, 0);
            atomicExch(&g_sy2, 0);
            atomicExch(&g_sy3, 0);
            atomicExch(&g_dn, 0);
        }
    }
}

// ---------------------------------------------------------------------------
// K2: exact kNN (one warp/query) + fused feat1 epilogue.
// DUAL-SEGMENT tiles; uniform trip count; reg-capped for occupancy.
#define BITONIC32(D, J)                                                       \
    {                                                                         \
        _Pragma("unroll")                                                     \
        for (int k = 2; k <= 32; k <<= 1) {                                   \
            _Pragma("unroll")                                                 \
            for (int st = k >> 1; st > 0; st >>= 1) {                         \
                float od = __shfl_xor_sync(FULL, D, st);                      \
                int   oj = __shfl_xor_sync(FULL, J, st);                      \
                bool up = ((lane & k) == 0);                                  \
                bool lo = ((lane & st) == 0);                                 \
                bool keepMin = (lo == up);                                    \
                bool take = keepMin ? (od < D) : (od > D);                    \
                D = take ? od : D;                                            \
                J = take ? oj : J;                                            \
            }                                                                 \
        }                                                                     \
    }

#define SCANPAIR(S00, S01, S10, S11)                                          \
    {                                                                         \
        int mlo = (lane < 16) ? (S00) : (S10);                                \
        int mhi = (lane < 16) ? (S01) : (S11);                                \
        int sub = lane & 15;                                                  \
        int it0 = ((S01) - (S00) + 15) >> 4;                                  \
        int it1 = ((S11) - (S10) + 15) >> 4;                                  \
        int iters = max(it0, it1);                                            \
        for (int it = 0; it < iters; ++it) {                                  \
            int j = mlo + it * 16 + sub;                                      \
            float d = FINF;                                                   \
            if (j < mhi) {                                                    \
                float4 cd = __ldg(&g_spts[j]);                                \
                d = fmaf(ax, cd.x, fmaf(ay, cd.y, fmaf(az, cd.z, cd.w + pw)));\
            }                                                                 \
            if (first) {                                                      \
                first = false;                                                \
                BITONIC32(d, j)                                               \
                bd = d; bj = j;                                               \
                kth = __shfl_sync(FULL, bd, KNN - 1);                         \
            } else {                                                          \
                unsigned msk = __ballot_sync(FULL, d < kth);                  \
                if (msk) {                                                    \
                    do {                                                      \
                        int src = __ffs(msk) - 1;                             \
                        msk &= msk - 1;                                       \
                        float dw = __shfl_sync(FULL, d, src);                 \
                        int   jw = __shfl_sync(FULL, j, src);                 \
                        float pbd = __shfl_up_sync(FULL, bd, 1);              \
                        int   pbj = __shfl_up_sync(FULL, bj, 1);              \
                        bool ins  = dw < bd;                                  \
                        bool pins = (lane > 0) && (dw < pbd);                 \
                        bd = ins ? (pins ? pbd : dw) : bd;                    \
                        bj = ins ? (pins ? pbj : jw) : bj;                    \
                    } while (msk);                                            \
                    kth = __shfl_sync(FULL, bd, KNN - 1);                     \
                }                                                             \
            }                                                                 \
        }                                                                     \
    }

__global__ __launch_bounds__(128, 10) void k_knng(const float* __restrict__ W1,
                                                  const float* __restrict__ b1) {
    const unsigned FULL = 0xFFFFFFFFu;
    int warp = (blockIdx.x * 128 + threadIdx.x) >> 5;
    int lane = threadIdx.x & 31;
    float4 p = g_spts[warp];
    float pw = p.w;
    float ax = -2.0f * p.x, ay = -2.0f * p.y, az = -2.0f * p.z;
    int cx = cell_of(p.x), cy = cell_of(p.y), cz = cell_of(p.z);

    float bd = FINF;
    int   bj = 0;
    float kth = FINF;
    bool  first = true;

    for (int m = 1; m < GRID; ++m) {
        int zlo = max(cz - m, 0), zhi = min(cz + m, GRID - 1);
        int ylo = max(cy - m, 0), yhi = min(cy + m, GRID - 1);
        int xlo = max(cx - m, 0), xhi = min(cx + m, GRID - 1);
        int ny = yhi - ylo + 1;
        int nrows = (zhi - zlo + 1) * ny;
        int rc = (m == 1) ? ((cz - zlo) * ny + (cy - ylo)) : 0;

        for (int rbase = 0; rbase < nrows; rbase += 32) {
            int rid = rbase + lane;
            int a0 = 0, a1 = 0, b0 = 0, b1r = 0;
            if (rid < nrows) {
                int z = zlo + rid / ny;
                int y = ylo + rid - (rid / ny) * ny;
                int rb = (z * GRID + y) * GRID;
                bool fullrow = (m == 1) || (abs(z - cz) == m) || (abs(y - cy) == m);
                if (fullrow) {
                    a0 = __ldg(&g_off[rb + xlo]);
                    a1 = __ldg(&g_off[rb + xhi + 1]);
                } else {
                    if (cx - m >= 0) {
                        a0 = __ldg(&g_off[rb + cx - m]);
                        a1 = __ldg(&g_off[rb + cx - m + 1]);
                    }
                    if (cx + m < GRID) {
                        b0 = __ldg(&g_off[rb + cx + m]);
                        b1r = __ldg(&g_off[rb + cx + m + 1]);
                    }
                }
            }
            unsigned nA = __ballot_sync(FULL, (rid < nrows) && (a1 > a0));
            unsigned nB = __ballot_sync(FULL, (rid < nrows) && (b1r > b0));
            bool fp = (m == 1) && (rbase == 0) && ((nA >> rc) & 1u);
            while (nA | nB) {
                int r0, r1 = -1;
                bool f0 = false, f1 = false;
                if (fp) { r0 = rc; nA &= ~(1u << rc); fp = false; }
                else if (nA) { r0 = __ffs(nA) - 1; nA &= nA - 1; }
                else { r0 = __ffs(nB) - 1; f0 = true; nB &= nB - 1; }
                if (nA) { r1 = __ffs(nA) - 1; nA &= nA - 1; }
                else if (nB) { r1 = __ffs(nB) - 1; f1 = true; nB &= nB - 1; }
                int s00 = __shfl_sync(FULL, f0 ? b0 : a0, r0);
                int s01 = __shfl_sync(FULL, f0 ? b1r : a1, r0);
                int s10 = 0, s11 = 0;
                if (r1 >= 0) {
                    s10 = __shfl_sync(FULL, f1 ? b0 : a0, r1);
                    s11 = __shfl_sync(FULL, f1 ? b1r : a1, r1);
                }
                SCANPAIR(s00, s01, s10, s11)
            }
        }

        float f0 = (xlo > 0)        ? (p.x - (BMIN + (float)xlo * CELLH))       : FINF;
        float f1 = (xhi < GRID - 1) ? ((BMIN + (float)(xhi + 1) * CELLH) - p.x) : FINF;
        float f2 = (ylo > 0)        ? (p.y - (BMIN + (float)ylo * CELLH))       : FINF;
        float f3 = (yhi < GRID - 1) ? ((BMIN + (float)(yhi + 1) * CELLH) - p.y) : FINF;
        float f4 = (zlo > 0)        ? (p.z - (BMIN + (float)zlo * CELLH))       : FINF;
        float f5 = (zhi < GRID - 1) ? ((BMIN + (float)(zhi + 1) * CELLH) - p.z) : FINF;
        float bb = fminf(fminf(fminf(f0, f1), fminf(f2, f3)), fminf(f4, f5));
        bb -= 1e-4f;
        if (kth <= bb * bb) break;
    }
    if (lane < KNN) g_idx[warp * KNN + lane] = bj;

    // Fused layer-1 projections: 2 h-columns per lane.
#pragma unroll
    for (int hh = 0; hh < 2; ++hh) {
        int h = lane + hh * 32;
        float wa0 = __ldg(&W1[0 * HDIM + h]);
        float wa1 = __ldg(&W1[1 * HDIM + h]);
        float wa2 = __ldg(&W1[2 * HDIM + h]);
        float wb0 = __ldg(&W1[3 * HDIM + h]);
        float wb1 = __ldg(&W1[4 * HDIM + h]);
        float wb2 = __ldg(&W1[5 * HDIM + h]);
        float v = fmaf(p.x, wb0, fmaf(p.y, wb1, p.z * wb2));
        float u = fmaf(p.x, wa0 - wb0, fmaf(p.y, wa1 - wb1, p.z * (wa2 - wb2)))
                  + __ldg(&b1[h]);
        g_A1[warp * HDIM + h] = u;
        g_B1[warp * HDIM + h] = v;
    }
}

// ---------------------------------------------------------------------------
// K3: fused gmax1 + layer-2 projections.
__global__ __launch_bounds__(256) void k_feat2(const float* __restrict__ W2,
                                               const float* __restrict__ b2) {
    __shared__ float sWu[HDIM * HDIM];
    __shared__ float sWv[HDIM * HDIM];
    __shared__ float sX[64 * HDIM];
    int tid = threadIdx.x;
    for (int e = tid; e < 64 * 16; e += 256) {
        int i = blockIdx.x * 64 + (e >> 4);
        int q = e & 15;
        const int4* row = reinterpret_cast<const int4*>(g_idx + i * KNN);
        float4 mx = make_float4(FNINF, FNINF, FNINF, FNINF);
#pragma unroll
        for (int k4 = 0; k4 < 4; ++k4) {
            int4 jj = __ldg(row + k4);
            int js[4] = {jj.x, jj.y, jj.z, jj.w};
#pragma unroll
            for (int e4 = 0; e4 < 4; ++e4) {
                float4 v = reinterpret_cast<const float4*>(g_B1)[js[e4] * 16 + q];
                mx.x = fmaxf(mx.x, v.x); mx.y = fmaxf(mx.y, v.y);
                mx.z = fmaxf(mx.z, v.z); mx.w = fmaxf(mx.w, v.w);
            }
        }
        float4 a = reinterpret_cast<const float4*>(g_A1)[i * 16 + q];
        float4 o;
        o.x = fmaxf(a.x + mx.x, 0.0f); o.y = fmaxf(a.y + mx.y, 0.0f);
        o.z = fmaxf(a.z + mx.z, 0.0f); o.w = fmaxf(a.w + mx.w, 0.0f);
        reinterpret_cast<float4*>(sX)[e] = o;
    }
    for (int e = tid; e < HDIM * HDIM; e += 256) {
        int j = e >> 6, h = e & 63;
        float wb = W2[(j + HDIM) * HDIM + h];
        sWv[e] = wb;
        sWu[e] = W2[j * HDIM + h] - wb;
    }
    __syncthreads();

    int ty = tid >> 4, q = tid & 15;
    float4 au[4], av[4];
#pragma unroll
    for (int k = 0; k < 4; ++k) {
        au[k] = make_float4(0.f, 0.f, 0.f, 0.f);
        av[k] = make_float4(0.f, 0.f, 0.f, 0.f);
    }
#pragma unroll 4
    for (int j = 0; j < HDIM; ++j) {
        float4 wu = reinterpret_cast<const float4*>(sWu)[j * 16 + q];
        float4 wv = reinterpret_cast<const float4*>(sWv)[j * 16 + q];
#pragma unroll
        for (int k = 0; k < 4; ++k) {
            float xj = sX[(ty * 4 + k) * HDIM + j];
            au[k].x = fmaf(xj, wu.x, au[k].x); au[k].y = fmaf(xj, wu.y, au[k].y);
            au[k].z = fmaf(xj, wu.z, au[k].z); au[k].w = fmaf(xj, wu.w, au[k].w);
            av[k].x = fmaf(xj, wv.x, av[k].x); av[k].y = fmaf(xj, wv.y, av[k].y);
            av[k].z = fmaf(xj, wv.z, av[k].z); av[k].w = fmaf(xj, wv.w, av[k].w);
        }
    }
    float4 bb = reinterpret_cast<const float4*>(b2)[q];
#pragma unroll
    for (int k = 0; k < 4; ++k) {
        int i = blockIdx.x * 64 + ty * 4 + k;
        au[k].x += bb.x; au[k].y += bb.y; au[k].z += bb.z; au[k].w += bb.w;
        reinterpret_cast<float4*>(g_A2)[i * 16 + q] = au[k];
        reinterpret_cast<float4*>(g_B2)[i * 16 + q] = av[k];
    }
}

// ---------------------------------------------------------------------------
// K4: h2 = relu(A2 + max_k B2[idx]) -> global max -> (last block) output.
__global__ __launch_bounds__(256) void k_gmax2(const float* __restrict__ Wc,
                                               const float* __restrict__ bc,
                                               float* __restrict__ out,
                                               int nblocks) {
    __shared__ int sg[HDIM];
    __shared__ bool amLast;
    if (threadIdx.x < HDIM) sg[threadIdx.x] = 0;
    __syncthreads();
    int gt = blockIdx.x * 256 + threadIdx.x;
    int i = gt >> 4, q = gt & 15;
    const int4* row = reinterpret_cast<const int4*>(g_idx + i * KNN);
    float4 m = make_float4(FNINF, FNINF, FNINF, FNINF);
#pragma unroll
    for (int k4 = 0; k4 < 4; ++k4) {
        int4 jj = __ldg(row + k4);
        int js[4] = {jj.x, jj.y, jj.z, jj.w};
#pragma unroll
        for (int e = 0; e < 4; ++e) {
            float4 v = reinterpret_cast<const float4*>(g_B2)[js[e] * 16 + q];
            m.x = fmaxf(m.x, v.x); m.y = fmaxf(m.y, v.y);
            m.z = fmaxf(m.z, v.z); m.w = fmaxf(m.w, v.w);
        }
    }
    float4 a = reinterpret_cast<const float4*>(g_A2)[i * 16 + q];
    float4 o;
    o.x = fmaxf(a.x + m.x, 0.0f); o.y = fmaxf(a.y + m.y, 0.0f);
    o.z = fmaxf(a.z + m.z, 0.0f); o.w = fmaxf(a.w + m.w, 0.0f);
    atomicMax(&sg[q * 4 + 0], __float_as_int(o.x));
    atomicMax(&sg[q * 4 + 1], __float_as_int(o.y));
    atomicMax(&sg[q * 4 + 2], __float_as_int(o.z));
    atomicMax(&sg[q * 4 + 3], __float_as_int(o.w));
    __syncthreads();
    if (threadIdx.x < HDIM) atomicMax(&g_gmax[threadIdx.x], sg[threadIdx.x]);

    __threadfence();
    if (threadIdx.x == 0) {
        int t = atomicAdd(&g_tick, 1);
        amLast = (t == nblocks - 1);
    }
    __syncthreads();
    if (amLast) {
        __shared__ float gv[HDIM];
        int c = threadIdx.x;
        if (c < HDIM) gv[c] = __int_as_float(atomicAdd(&g_gmax[c], 0));
        __syncthreads();
        if (c < CDIM) {
            float acc = bc[c];
#pragma unroll
            for (int h = 0; h < HDIM; ++h)
                acc = fmaf(gv[h], Wc[h * CDIM + c], acc);
            out[c] = acc;
        }
        if (c < HDIM) g_gmax[c] = 0;
        if (c == 0) g_tick = 0;
    }
}

// ---------------------------------------------------------------------------
extern "C" void kernel_launch(void* const* d_in, const int* in_sizes, int n_in,
                              void* d_out, int out_size) {
    const float* pos = (const float*)d_in[0];
    // d_in[1] = batch (all zeros, num_segments=1) -> unused
    const float* W1 = (const float*)d_in[2];
    const float* b1 = (const float*)d_in[3];
    const float* W2 = (const float*)d_in[4];
    const float* b2 = (const float*)d_in[5];
    const float* Wc = (const float*)d_in[6];
    const float* bc = (const float*)d_in[7];
    float* out = (float*)d_out;

    k_build<<<64, 256>>>(pos);                                // 0
    k_knng<<<NPTS * 32 / 128, 128>>>(W1, b1);                 // 1
    k_feat2<<<NPTS / 64, 256>>>(W2, b2);                      // 2
    k_gmax2<<<NPTS * 16 / 256, 256>>>(Wc, bc, out,
                                      NPTS * 16 / 256);       // 3  <- ncu slot
}

// round 15
// speedup vs baseline: 3.3707x; 1.0099x over previous
#include <cuda_runtime.h>

// Problem constants
#define NPTS 16384
#define KNN  16
#define HDIM 64
#define CDIM 10

// Spatial grid: h=0.3 over [-4.8, 4.8]^3
#define GRID  32
#define NCELL (GRID * GRID * GRID)      // 32768
#define BMIN  (-4.8f)
#define CELLH 0.3f
#define INVH  (1.0f / 0.3f)

#define FINF  __int_as_float(0x7f800000)
#define FNINF __int_as_float(0xff800000)

#define TAILBLK 256   // persistent tail kernel: co-resident (48KB smem -> 4/SM)

// ---- scratch (__device__ globals; zero-initialized at load) ----
__device__ int    g_cnt[NCELL];      // re-zeroed inside k_build each run
__device__ int    g_off[NCELL + 4];
__device__ int    g_cur[NCELL];
__device__ int    g_bsum[64];
__device__ float4 g_spts[NPTS];
__device__ int    g_idx[NPTS * KNN];
__device__ float  g_A1[NPTS * HDIM];
__device__ float  g_B1[NPTS * HDIM];
__device__ float  g_A2[NPTS * HDIM];
__device__ float  g_B2[NPTS * HDIM];
__device__ int    g_gmax[HDIM];      // re-zeroed by last tail block
__device__ int    g_tick;            // ticket; re-zeroed by last tail block
__device__ int    g_fb;              // tail grid barrier; re-zeroed by last block
__device__ int    g_sy1, g_sy2, g_sy3, g_dn;   // k_build barriers (self-reset)

__device__ __forceinline__ int cell_of(float v) {
    int c = (int)floorf((v - BMIN) * INVH);
    return min(max(c, 0), GRID - 1);
}

// software grid barrier for a co-resident grid of n blocks
__device__ __forceinline__ void gbar(int* ctr, int n) {
    __syncthreads();
    if (threadIdx.x == 0) {
        __threadfence();
        atomicAdd(ctr, 1);
        while (atomicAdd(ctr, 0) < n) { }
    }
    __syncthreads();
}

// ---------------------------------------------------------------------------
// K1: fused prep + histogram + scan + scatter. 64 co-resident blocks.
__global__ __launch_bounds__(256) void k_build(const float* __restrict__ pos) {
    __shared__ int s[256];
    __shared__ int sb[64];
    int t = threadIdx.x, b = blockIdx.x;

    int i = b * 256 + t;
    float x = pos[i * 3 + 0];
    float y = pos[i * 3 + 1];
    float z = pos[i * 3 + 2];
    float w = fmaf(z, z, fmaf(y, y, x * x));
    int c = (cell_of(z) * GRID + cell_of(y)) * GRID + cell_of(x);
    atomicAdd(&g_cnt[c], 1);
    gbar(&g_sy1, 64);

    int4 cc = make_int4(0, 0, 0, 0);
    int sum = 0;
    if (t < 128) {
        cc = reinterpret_cast<const int4*>(g_cnt)[b * 128 + t];
        sum = cc.x + cc.y + cc.z + cc.w;
    }
    s[t] = sum;
    __syncthreads();
    for (int off = 1; off < 256; off <<= 1) {
        int u = (t >= off) ? s[t - off] : 0;
        __syncthreads();
        s[t] += u;
        __syncthreads();
    }
    int excl = s[t] - sum;
    if (t == 255) g_bsum[b] = s[255];
    gbar(&g_sy2, 64);

    if (t < 64) sb[t] = g_bsum[t];
    __syncthreads();
    if (t == 0) {
        int r = 0;
        for (int k = 0; k < 64; ++k) { int v = sb[k]; sb[k] = r; r += v; }
    }
    __syncthreads();
    int base = sb[b] + excl;
    if (t < 128) {
        int4 o = make_int4(base, base + cc.x, base + cc.x + cc.y,
                           base + cc.x + cc.y + cc.z);
        reinterpret_cast<int4*>(g_off)[b * 128 + t] = o;
        reinterpret_cast<int4*>(g_cur)[b * 128 + t] = o;
        reinterpret_cast<int4*>(g_cnt)[b * 128 + t] = make_int4(0, 0, 0, 0);
    }
    if (b == 63 && t == 255) g_off[NCELL] = NPTS;
    gbar(&g_sy3, 64);

    int slot = atomicAdd(&g_cur[c], 1);
    g_spts[slot] = make_float4(x, y, z, w);

    __syncthreads();
    if (t == 0) {
        __threadfence();
        int d = atomicAdd(&g_dn, 1);
        if (d == 63) {
            atomicExch(&g_sy1, 0);
            atomicExch(&g_sy2, 0);
            atomicExch(&g_sy3, 0);
            atomicExch(&g_dn, 0);
        }
    }
}

// ---------------------------------------------------------------------------
// K2: exact kNN (one warp/query) + fused feat1 epilogue.
#define BITONIC32(D, J)                                                       \
    {                                                                         \
        _Pragma("unroll")                                                     \
        for (int k = 2; k <= 32; k <<= 1) {                                   \
            _Pragma("unroll")                                                 \
            for (int st = k >> 1; st > 0; st >>= 1) {                         \
                float od = __shfl_xor_sync(FULL, D, st);                      \
                int   oj = __shfl_xor_sync(FULL, J, st);                      \
                bool up = ((lane & k) == 0);                                  \
                bool lo = ((lane & st) == 0);                                 \
                bool keepMin = (lo == up);                                    \
                bool take = keepMin ? (od < D) : (od > D);                    \
                D = take ? od : D;                                            \
                J = take ? oj : J;                                            \
            }                                                                 \
        }                                                                     \
    }

#define SCANPAIR(S00, S01, S10, S11)                                          \
    {                                                                         \
        int mlo = (lane < 16) ? (S00) : (S10);                                \
        int mhi = (lane < 16) ? (S01) : (S11);                                \
        int sub = lane & 15;                                                  \
        int it0 = ((S01) - (S00) + 15) >> 4;                                  \
        int it1 = ((S11) - (S10) + 15) >> 4;                                  \
        int iters = max(it0, it1);                                            \
        for (int it = 0; it < iters; ++it) {                                  \
            int j = mlo + it * 16 + sub;                                      \
            float d = FINF;                                                   \
            if (j < mhi) {                                                    \
                float4 cd = __ldg(&g_spts[j]);                                \
                d = fmaf(ax, cd.x, fmaf(ay, cd.y, fmaf(az, cd.z, cd.w + pw)));\
            }                                                                 \
            if (first) {                                                      \
                first = false;                                                \
                BITONIC32(d, j)                                               \
                bd = d; bj = j;                                               \
                kth = __shfl_sync(FULL, bd, KNN - 1);                         \
            } else {                                                          \
                unsigned msk = __ballot_sync(FULL, d < kth);                  \
                if (msk) {                                                    \
                    do {                                                      \
                        int src = __ffs(msk) - 1;                             \
                        msk &= msk - 1;                                       \
                        float dw = __shfl_sync(FULL, d, src);                 \
                        int   jw = __shfl_sync(FULL, j, src);                 \
                        float pbd = __shfl_up_sync(FULL, bd, 1);              \
                        int   pbj = __shfl_up_sync(FULL, bj, 1);              \
                        bool ins  = dw < bd;                                  \
                        bool pins = (lane > 0) && (dw < pbd);                 \
                        bd = ins ? (pins ? pbd : dw) : bd;                    \
                        bj = ins ? (pins ? pbj : jw) : bj;                    \
                    } while (msk);                                            \
                    kth = __shfl_sync(FULL, bd, KNN - 1);                     \
                }                                                             \
            }                                                                 \
        }                                                                     \
    }

__global__ __launch_bounds__(128, 10) void k_knng(const float* __restrict__ W1,
                                                  const float* __restrict__ b1) {
    const unsigned FULL = 0xFFFFFFFFu;
    int warp = (blockIdx.x * 128 + threadIdx.x) >> 5;
    int lane = threadIdx.x & 31;
    float4 p = g_spts[warp];
    float pw = p.w;
    float ax = -2.0f * p.x, ay = -2.0f * p.y, az = -2.0f * p.z;
    int cx = cell_of(p.x), cy = cell_of(p.y), cz = cell_of(p.z);

    float bd = FINF;
    int   bj = 0;
    float kth = FINF;
    bool  first = true;

    for (int m = 1; m < GRID; ++m) {
        int zlo = max(cz - m, 0), zhi = min(cz + m, GRID - 1);
        int ylo = max(cy - m, 0), yhi = min(cy + m, GRID - 1);
        int xlo = max(cx - m, 0), xhi = min(cx + m, GRID - 1);
        int ny = yhi - ylo + 1;
        int nrows = (zhi - zlo + 1) * ny;
        int rc = (m == 1) ? ((cz - zlo) * ny + (cy - ylo)) : 0;

        for (int rbase = 0; rbase < nrows; rbase += 32) {
            int rid = rbase + lane;
            int a0 = 0, a1 = 0, b0 = 0, b1r = 0;
            if (rid < nrows) {
                int z = zlo + rid / ny;
                int y = ylo + rid - (rid / ny) * ny;
                int rb = (z * GRID + y) * GRID;
                bool fullrow = (m == 1) || (abs(z - cz) == m) || (abs(y - cy) == m);
                if (fullrow) {
                    a0 = __ldg(&g_off[rb + xlo]);
                    a1 = __ldg(&g_off[rb + xhi + 1]);
                } else {
                    if (cx - m >= 0) {
                        a0 = __ldg(&g_off[rb + cx - m]);
                        a1 = __ldg(&g_off[rb + cx - m + 1]);
                    }
                    if (cx + m < GRID) {
                        b0 = __ldg(&g_off[rb + cx + m]);
                        b1r = __ldg(&g_off[rb + cx + m + 1]);
                    }
                }
            }
            unsigned nA = __ballot_sync(FULL, (rid < nrows) && (a1 > a0));
            unsigned nB = __ballot_sync(FULL, (rid < nrows) && (b1r > b0));
            bool fp = (m == 1) && (rbase == 0) && ((nA >> rc) & 1u);
            while (nA | nB) {
                int r0, r1 = -1;
                bool f0 = false, f1 = false;
                if (fp) { r0 = rc; nA &= ~(1u << rc); fp = false; }
                else if (nA) { r0 = __ffs(nA) - 1; nA &= nA - 1; }
                else { r0 = __ffs(nB) - 1; f0 = true; nB &= nB - 1; }
                if (nA) { r1 = __ffs(nA) - 1; nA &= nA - 1; }
                else if (nB) { r1 = __ffs(nB) - 1; f1 = true; nB &= nB - 1; }
                int s00 = __shfl_sync(FULL, f0 ? b0 : a0, r0);
                int s01 = __shfl_sync(FULL, f0 ? b1r : a1, r0);
                int s10 = 0, s11 = 0;
                if (r1 >= 0) {
                    s10 = __shfl_sync(FULL, f1 ? b0 : a0, r1);
                    s11 = __shfl_sync(FULL, f1 ? b1r : a1, r1);
                }
                SCANPAIR(s00, s01, s10, s11)
            }
        }

        float f0 = (xlo > 0)        ? (p.x - (BMIN + (float)xlo * CELLH))       : FINF;
        float f1 = (xhi < GRID - 1) ? ((BMIN + (float)(xhi + 1) * CELLH) - p.x) : FINF;
        float f2 = (ylo > 0)        ? (p.y - (BMIN + (float)ylo * CELLH))       : FINF;
        float f3 = (yhi < GRID - 1) ? ((BMIN + (float)(yhi + 1) * CELLH) - p.y) : FINF;
        float f4 = (zlo > 0)        ? (p.z - (BMIN + (float)zlo * CELLH))       : FINF;
        float f5 = (zhi < GRID - 1) ? ((BMIN + (float)(zhi + 1) * CELLH) - p.z) : FINF;
        float bb = fminf(fminf(fminf(f0, f1), fminf(f2, f3)), fminf(f4, f5));
        bb -= 1e-4f;
        if (kth <= bb * bb) break;
    }
    if (lane < KNN) g_idx[warp * KNN + lane] = bj;

#pragma unroll
    for (int hh = 0; hh < 2; ++hh) {
        int h = lane + hh * 32;
        float wa0 = __ldg(&W1[0 * HDIM + h]);
        float wa1 = __ldg(&W1[1 * HDIM + h]);
        float wa2 = __ldg(&W1[2 * HDIM + h]);
        float wb0 = __ldg(&W1[3 * HDIM + h]);
        float wb1 = __ldg(&W1[4 * HDIM + h]);
        float wb2 = __ldg(&W1[5 * HDIM + h]);
        float v = fmaf(p.x, wb0, fmaf(p.y, wb1, p.z * wb2));
        float u = fmaf(p.x, wa0 - wb0, fmaf(p.y, wa1 - wb1, p.z * (wa2 - wb2)))
                  + __ldg(&b1[h]);
        g_A1[warp * HDIM + h] = u;
        g_B1[warp * HDIM + h] = v;
    }
}

// ---------------------------------------------------------------------------
// K3: persistent tail: [gmax1 + feat2] -> grid barrier -> [gmax2 + output].
// 256 co-resident blocks (48KB smem -> 4/SM on 148 SMs).
__global__ __launch_bounds__(256) void k_tail(const float* __restrict__ W2,
                                              const float* __restrict__ b2,
                                              const float* __restrict__ Wc,
                                              const float* __restrict__ bc,
                                              float* __restrict__ out) {
    __shared__ float sWu[HDIM * HDIM];
    __shared__ float sWv[HDIM * HDIM];
    __shared__ float sX[64 * HDIM];
    int tid = threadIdx.x;

    // Phase A: h1 tile = relu(A1 + max_k B1[idx]) into shared
    for (int e = tid; e < 64 * 16; e += 256) {
        int i = blockIdx.x * 64 + (e >> 4);
        int q = e & 15;
        const int4* row = reinterpret_cast<const int4*>(g_idx + i * KNN);
        float4 mx = make_float4(FNINF, FNINF, FNINF, FNINF);
#pragma unroll
        for (int k4 = 0; k4 < 4; ++k4) {
            int4 jj = __ldg(row + k4);
            int js[4] = {jj.x, jj.y, jj.z, jj.w};
#pragma unroll
            for (int e4 = 0; e4 < 4; ++e4) {
                float4 v = reinterpret_cast<const float4*>(g_B1)[js[e4] * 16 + q];
                mx.x = fmaxf(mx.x, v.x); mx.y = fmaxf(mx.y, v.y);
                mx.z = fmaxf(mx.z, v.z); mx.w = fmaxf(mx.w, v.w);
            }
        }
        float4 a = reinterpret_cast<const float4*>(g_A1)[i * 16 + q];
        float4 o;
        o.x = fmaxf(a.x + mx.x, 0.0f); o.y = fmaxf(a.y + mx.y, 0.0f);
        o.z = fmaxf(a.z + mx.z, 0.0f); o.w = fmaxf(a.w + mx.w, 0.0f);
        reinterpret_cast<float4*>(sX)[e] = o;
    }
    for (int e = tid; e < HDIM * HDIM; e += 256) {
        int j = e >> 6, h = e & 63;
        float wb = W2[(j + HDIM) * HDIM + h];
        sWv[e] = wb;
        sWu[e] = W2[j * HDIM + h] - wb;
    }
    __syncthreads();

    // Phase B: A2 = h1@(W2a-W2b)+b2, B2 = h1@W2b
    {
        int ty = tid >> 4, q = tid & 15;
        float4 au[4], av[4];
#pragma unroll
        for (int k = 0; k < 4; ++k) {
            au[k] = make_float4(0.f, 0.f, 0.f, 0.f);
            av[k] = make_float4(0.f, 0.f, 0.f, 0.f);
        }
#pragma unroll 4
        for (int j = 0; j < HDIM; ++j) {
            float4 wu = reinterpret_cast<const float4*>(sWu)[j * 16 + q];
            float4 wv = reinterpret_cast<const float4*>(sWv)[j * 16 + q];
#pragma unroll
            for (int k = 0; k < 4; ++k) {
                float xj = sX[(ty * 4 + k) * HDIM + j];
                au[k].x = fmaf(xj, wu.x, au[k].x); au[k].y = fmaf(xj, wu.y, au[k].y);
                au[k].z = fmaf(xj, wu.z, au[k].z); au[k].w = fmaf(xj, wu.w, au[k].w);
                av[k].x = fmaf(xj, wv.x, av[k].x); av[k].y = fmaf(xj, wv.y, av[k].y);
                av[k].z = fmaf(xj, wv.z, av[k].z); av[k].w = fmaf(xj, wv.w, av[k].w);
            }
        }
        float4 bb = reinterpret_cast<const float4*>(b2)[q];
#pragma unroll
        for (int k = 0; k < 4; ++k) {
            int i = blockIdx.x * 64 + ty * 4 + k;
            au[k].x += bb.x; au[k].y += bb.y; au[k].z += bb.z; au[k].w += bb.w;
            reinterpret_cast<float4*>(g_A2)[i * 16 + q] = au[k];
            reinterpret_cast<float4*>(g_B2)[i * 16 + q] = av[k];
        }
    }

    // grid barrier: all A2/B2 visible before neighbor gathers
    gbar(&g_fb, TAILBLK);

    // Phase C: h2 = relu(A2 + max_k B2[idx]) -> block max -> global max.
    // 4 work items per thread (262144 / (256*256)) for deep MLP.
    __shared__ int sg[HDIM];
    if (tid < HDIM) sg[tid] = 0;
    __syncthreads();
#pragma unroll
    for (int ch = 0; ch < 4; ++ch) {
        int gt = (ch * TAILBLK + blockIdx.x) * 256 + tid;
        int i = gt >> 4, q = gt & 15;
        const int4* row = reinterpret_cast<const int4*>(g_idx + i * KNN);
        float4 m = make_float4(FNINF, FNINF, FNINF, FNINF);
#pragma unroll
        for (int k4 = 0; k4 < 4; ++k4) {
            int4 jj = __ldg(row + k4);
            int js[4] = {jj.x, jj.y, jj.z, jj.w};
#pragma unroll
            for (int e = 0; e < 4; ++e) {
                float4 v = reinterpret_cast<const float4*>(g_B2)[js[e] * 16 + q];
                m.x = fmaxf(m.x, v.x); m.y = fmaxf(m.y, v.y);
                m.z = fmaxf(m.z, v.z); m.w = fmaxf(m.w, v.w);
            }
        }
        float4 a = reinterpret_cast<const float4*>(g_A2)[i * 16 + q];
        float4 o;
        o.x = fmaxf(a.x + m.x, 0.0f); o.y = fmaxf(a.y + m.y, 0.0f);
        o.z = fmaxf(a.z + m.z, 0.0f); o.w = fmaxf(a.w + m.w, 0.0f);
        atomicMax(&sg[q * 4 + 0], __float_as_int(o.x));
        atomicMax(&sg[q * 4 + 1], __float_as_int(o.y));
        atomicMax(&sg[q * 4 + 2], __float_as_int(o.z));
        atomicMax(&sg[q * 4 + 3], __float_as_int(o.w));
    }
    __syncthreads();
    if (tid < HDIM) atomicMax(&g_gmax[tid], sg[tid]);

    // ticket: last block emits output, restores invariants
    __shared__ bool amLast;
    __threadfence();
    if (tid == 0) {
        int t = atomicAdd(&g_tick, 1);
        amLast = (t == TAILBLK - 1);
    }
    __syncthreads();
    if (amLast) {
        __shared__ float gv[HDIM];
        int c = tid;
        if (c < HDIM) gv[c] = __int_as_float(atomicAdd(&g_gmax[c], 0));
        __syncthreads();
        if (c < CDIM) {
            float acc = bc[c];
#pragma unroll
            for (int h = 0; h < HDIM; ++h)
                acc = fmaf(gv[h], Wc[h * CDIM + c], acc);
            out[c] = acc;
        }
        if (c < HDIM) g_gmax[c] = 0;
        if (c == 0) { g_tick = 0; atomicExch(&g_fb, 0); }
    }
}

// ---------------------------------------------------------------------------
extern "C" void kernel_launch(void* const* d_in, const int* in_sizes, int n_in,
                              void* d_out, int out_size) {
    const float* pos = (const float*)d_in[0];
    // d_in[1] = batch (all zeros, num_segments=1) -> unused
    const float* W1 = (const float*)d_in[2];
    const float* b1 = (const float*)d_in[3];
    const float* W2 = (const float*)d_in[4];
    const float* b2 = (const float*)d_in[5];
    const float* Wc = (const float*)d_in[6];
    const float* bc = (const float*)d_in[7];
    float* out = (float*)d_out;

    k_build<<<64, 256>>>(pos);                                // 0
    k_knng<<<NPTS * 32 / 128, 128>>>(W1, b1);                 // 1
    k_tail<<<TAILBLK, 256>>>(W2, b2, Wc, bc, out);            // 2
}